// round 2
// baseline (speedup 1.0000x reference)
#include <cuda_runtime.h>
#include <math.h>

// ---------------- problem constants (fixed by setup_inputs) ----------------
#define NB     32     // batch
#define C_IN   64     // input channels
#define HW     128    // spatial H = W
#define OCH    256    // output channels
#define HASH   8      // num hashes
#define D_A    603    // (64+3)*9
#define KW2    576    // 64*9
#define MPOW   27     // appended power dims (3*9)
#define TSZ    512    // table size
#define RADIUS 4.0f
#define UBND   0.99f

// ---------------- device scratch (no allocations allowed) ------------------
__device__ int   g_hist[HASH * TSZ];
__device__ float g_norm[OCH];
__device__ float g_scale;
__device__ int   g_kbuckets[HASH * OCH];
__device__ int   g_voted[HASH];
__device__ int   g_mask[OCH];

// ---------------- 0: zero the global histogram -----------------------------
__global__ void zero_hist_kernel() {
    int i = blockIdx.x * blockDim.x + threadIdx.x;
    if (i < HASH * TSZ) g_hist[i] = 0;
}

// ---------------- 1: kernel-row norms + global scale ------------------------
__global__ void norms_kernel(const float* __restrict__ w) {
    __shared__ float sn[256];
    int o = threadIdx.x;             // 256 threads == 256 kernel rows
    const float* row = w + o * KW2;
    float s = 0.f;
    for (int j = 0; j < KW2; j++) { float v = row[j]; s += v * v; }
    float nrm = sqrtf(s);
    g_norm[o] = nrm;
    sn[o] = nrm;
    __syncthreads();
    for (int st = 128; st > 0; st >>= 1) {
        if (o < st) sn[o] = fmaxf(sn[o], sn[o + st]);
        __syncthreads();
    }
    if (o == 0) g_scale = UBND / sn[0];
}

// ---------------- 2: bucket id of every kernel under every hash -------------
// one warp per (h, o) pair; 2048 warps total
__global__ void kbuckets_kernel(const float* __restrict__ w,
                                const float* __restrict__ a,
                                const float* __restrict__ b) {
    int wid  = (blockIdx.x * blockDim.x + threadIdx.x) >> 5;
    int lane = threadIdx.x & 31;
    if (wid >= HASH * OCH) return;
    int h = wid >> 8;        // /256
    int o = wid & 255;

    const float* ar = a + h * D_A;
    const float* wr = w + o * KW2;
    float s = 0.f;
    for (int j = lane; j < KW2; j += 32) s += ar[j] * wr[j];
    #pragma unroll
    for (int off = 16; off; off >>= 1) s += __shfl_down_sync(0xffffffffu, s, off);

    if (lane == 0) {
        float dot = g_scale * s;                 // a_flat . scaled_row
        float t = g_scale * g_norm[o];           // sn
        #pragma unroll 1
        for (int p = 0; p < MPOW; p++) {         // sn^(2^1) ... sn^(2^27)
            t = t * t;
            dot += ar[KW2 + p] * t;
        }
        float v  = floorf((dot + b[h]) / RADIUS);
        int   bk = (int)fabsf(fmodf(v, (float)TSZ));
        g_kbuckets[h * OCH + o] = bk;
    }
}

// ---------------- 3: vote — hash conv of padded input + histogram -----------
// tile 32x32 output px; 256 threads; each thread: 4 px (column of 4 rows),
// all 8 hash accumulators in registers.
#define VT 32
__global__ void vote_kernel(const float* __restrict__ x,
                            const float* __restrict__ a,
                            const float* __restrict__ b) {
    __shared__ float xs[4][VT + 2][36];       // 4-ch chunk, padded input tile
    __shared__ float ws[4][9][HASH];          // hash weights for this chunk
    __shared__ float sb[HASH];
    __shared__ int   shist[HASH * TSZ];

    int tid = threadIdx.x;
    int n   = blockIdx.z;
    int x0  = blockIdx.x * VT;
    int y0  = blockIdx.y * VT;

    for (int e = tid; e < HASH * TSZ; e += 256) shist[e] = 0;
    if (tid < HASH) sb[tid] = b[tid];

    int col = tid & 31;
    int rb  = (tid >> 5) << 2;

    float acc[HASH][4];
    #pragma unroll
    for (int h = 0; h < HASH; h++)
        #pragma unroll
        for (int p = 0; p < 4; p++) acc[h][p] = 0.f;

    // 67 channels (last 3 are constant 0.5 inside the image, 0 in padding),
    // processed as 17 chunks of 4 (68th channel is zero-padded).
    for (int c0 = 0; c0 < 68; c0 += 4) {
        __syncthreads();
        for (int e = tid; e < 4 * 34 * 34; e += 256) {
            int c   = e / (34 * 34);
            int rem = e % (34 * 34);
            int ry = rem / 34, rx = rem % 34;
            int cg = c0 + c;
            int gy = y0 - 1 + ry, gx = x0 - 1 + rx;
            float v = 0.f;
            if (cg < 67 && gy >= 0 && gy < HW && gx >= 0 && gx < HW)
                v = (cg < C_IN) ? x[((n * C_IN + cg) * HW + gy) * HW + gx] : 0.5f;
            xs[c][ry][rx] = v;
        }
        for (int e = tid; e < 4 * 9 * HASH; e += 256) {
            int h   = e % HASH;
            int rem = e / HASH;
            int c = rem / 9, khw = rem % 9;
            int cg = c0 + c;
            ws[c][khw][h] = (cg < 67) ? a[h * D_A + cg * 9 + khw] : 0.f;
        }
        __syncthreads();

        #pragma unroll
        for (int c = 0; c < 4; c++) {
            #pragma unroll
            for (int kh = 0; kh < 3; kh++) {
                #pragma unroll
                for (int kw = 0; kw < 3; kw++) {
                    float wv[HASH];
                    #pragma unroll
                    for (int h = 0; h < HASH; h++) wv[h] = ws[c][kh * 3 + kw][h];
                    float xv[4];
                    #pragma unroll
                    for (int p = 0; p < 4; p++) xv[p] = xs[c][rb + p + kh][col + kw];
                    #pragma unroll
                    for (int h = 0; h < HASH; h++)
                        #pragma unroll
                        for (int p = 0; p < 4; p++) acc[h][p] += wv[h] * xv[p];
                }
            }
        }
    }
    __syncthreads();

    #pragma unroll
    for (int h = 0; h < HASH; h++) {
        #pragma unroll
        for (int p = 0; p < 4; p++) {
            float v  = floorf((acc[h][p] + sb[h]) / RADIUS);
            int   bk = (int)fabsf(fmodf(v, (float)TSZ));
            atomicAdd(&shist[h * TSZ + bk], 1);
        }
    }
    __syncthreads();
    for (int e = tid; e < HASH * TSZ; e += 256) {
        int v = shist[e];
        if (v) atomicAdd(&g_hist[e], v);
    }
}

// ---------------- 4: argmax per hash (ties -> lowest index, like jnp) -------
__global__ void argmax_kernel() {
    int w    = threadIdx.x >> 5;   // 8 warps, one per hash
    int lane = threadIdx.x & 31;
    int best = -1, bidx = 0;
    for (int j = lane; j < TSZ; j += 32) {
        int c = g_hist[w * TSZ + j];
        if (c > best) { best = c; bidx = j; }   // strict > keeps lowest j
    }
    #pragma unroll
    for (int off = 16; off; off >>= 1) {
        int ob = __shfl_down_sync(0xffffffffu, best, off);
        int oi = __shfl_down_sync(0xffffffffu, bidx, off);
        if (ob > best || (ob == best && oi < bidx)) { best = ob; bidx = oi; }
    }
    if (lane == 0) g_voted[w] = bidx;
}

// ---------------- 5: active-channel mask -------------------------------------
__global__ void mask_kernel() {
    __shared__ int sv[HASH];
    if (threadIdx.x < HASH) sv[threadIdx.x] = g_voted[threadIdx.x];
    __syncthreads();
    int o = threadIdx.x;
    int m = 0;
    #pragma unroll
    for (int h = 0; h < HASH; h++) {
        int kb = g_kbuckets[h * OCH + o];
        #pragma unroll
        for (int j = 0; j < HASH; j++) m |= (kb == sv[j]);
    }
    g_mask[o] = m;
}

// ---------------- 6: main conv (FFMA-bound direct conv) ----------------------
// block: 16x16 px tile x 32 output channels; 256 threads.
// thread: 8 oc x 4 px (column) = 32 accumulators.
#define CT 16
__global__ void conv_kernel(const float* __restrict__ x,
                            const float* __restrict__ w,
                            float* __restrict__ out) {
    __shared__ float xs[8][CT + 2][20];   // row stride 20 -> conflict-free
    __shared__ float ws[8][9][32];
    __shared__ float smask[32];

    int tid = threadIdx.x;
    int z   = blockIdx.z;
    int ocg = z & 7;
    int n   = z >> 3;
    int ocbase = ocg * 32;
    int x0 = blockIdx.x * CT, y0 = blockIdx.y * CT;

    if (tid < 32) smask[tid] = g_mask[ocbase + tid] ? 1.f : 0.f;
    __syncthreads();

    bool any = false;
    #pragma unroll
    for (int i = 0; i < 32; i++) any |= (smask[i] != 0.f);

    int ocsub = tid >> 6;         // 0..3  -> oc group of 8
    int pxg   = tid & 63;
    int col   = pxg & 15;         // 0..15
    int rb    = (pxg >> 4) << 2;  // 0,4,8,12

    if (!any) {                   // whole oc-group inactive: exact zeros
        #pragma unroll
        for (int i = 0; i < 8; i++) {
            int oc = ocbase + ocsub * 8 + i;
            #pragma unroll
            for (int p = 0; p < 4; p++)
                out[((n * OCH + oc) * HW + y0 + rb + p) * HW + x0 + col] = 0.f;
        }
        return;
    }

    float acc[8][4];
    #pragma unroll
    for (int i = 0; i < 8; i++)
        #pragma unroll
        for (int p = 0; p < 4; p++) acc[i][p] = 0.f;

    for (int c0 = 0; c0 < C_IN; c0 += 8) {
        __syncthreads();
        for (int e = tid; e < 8 * 18 * 18; e += 256) {
            int c   = e / 324;
            int rem = e % 324;
            int ry = rem / 18, rx = rem % 18;
            int gy = y0 - 1 + ry, gx = x0 - 1 + rx;
            float v = 0.f;
            if (gy >= 0 && gy < HW && gx >= 0 && gx < HW)
                v = x[((n * C_IN + c0 + c) * HW + gy) * HW + gx];
            xs[c][ry][rx] = v;
        }
        for (int e = tid; e < 8 * 9 * 32; e += 256) {
            int oc  = e / 72;
            int rem = e % 72;
            int c = rem / 9, khw = rem % 9;
            ws[c][khw][oc] = w[(ocbase + oc) * KW2 + (c0 + c) * 9 + khw];
        }
        __syncthreads();

        #pragma unroll 2
        for (int c = 0; c < 8; c++) {
            #pragma unroll
            for (int kh = 0; kh < 3; kh++) {
                #pragma unroll
                for (int kw = 0; kw < 3; kw++) {
                    float wv[8];
                    #pragma unroll
                    for (int i = 0; i < 8; i++) wv[i] = ws[c][kh * 3 + kw][ocsub * 8 + i];
                    float xv[4];
                    #pragma unroll
                    for (int p = 0; p < 4; p++) xv[p] = xs[c][rb + p + kh][col + kw];
                    #pragma unroll
                    for (int i = 0; i < 8; i++)
                        #pragma unroll
                        for (int p = 0; p < 4; p++) acc[i][p] += wv[i] * xv[p];
                }
            }
        }
    }

    #pragma unroll
    for (int i = 0; i < 8; i++) {
        float m  = smask[ocsub * 8 + i];
        int   oc = ocbase + ocsub * 8 + i;
        #pragma unroll
        for (int p = 0; p < 4; p++)
            out[((n * OCH + oc) * HW + y0 + rb + p) * HW + x0 + col] = acc[i][p] * m;
    }
}

// ---------------- launch ------------------------------------------------------
extern "C" void kernel_launch(void* const* d_in, const int* in_sizes, int n_in,
                              void* d_out, int out_size) {
    const float* x = (const float*)d_in[0];   // [32,64,128,128]
    const float* w = (const float*)d_in[1];   // [256,64,3,3]
    const float* a = (const float*)d_in[2];   // [8,67,3,3]
    const float* b = (const float*)d_in[3];   // [8]
    float* out = (float*)d_out;               // [32,256,128,128]

    zero_hist_kernel<<<16, 256>>>();
    norms_kernel<<<1, 256>>>(w);
    kbuckets_kernel<<<256, 256>>>(w, a, b);
    vote_kernel<<<dim3(4, 4, NB), 256>>>(x, a, b);
    argmax_kernel<<<1, 256>>>();
    mask_kernel<<<1, 256>>>();
    conv_kernel<<<dim3(HW / CT, HW / CT, NB * 8), 256>>>(x, w, out);
}

// round 3
// speedup vs baseline: 1.0009x; 1.0009x over previous
#include <cuda_runtime.h>
#include <math.h>

// ---------------- problem constants (fixed by setup_inputs) ----------------
#define NB     32     // batch
#define C_IN   64     // input channels
#define HW     128    // spatial H = W
#define OCH    256    // output channels
#define HASH   8      // num hashes
#define D_A    603    // (64+3)*9
#define KW2    576    // 64*9
#define MPOW   27     // appended power dims (3*9)
#define TSZ    512    // table size
#define RADIUS 4.0f
#define UBND   0.99f

// ---------------- device scratch (no allocations allowed) ------------------
__device__ int   g_hist[HASH * TSZ];
__device__ float g_norm[OCH];
__device__ float g_scale;
__device__ int   g_kbuckets[HASH * OCH];
__device__ int   g_voted[HASH];
__device__ int   g_mask[OCH];

// ---------------- 0: zero the global histogram -----------------------------
__global__ void zero_hist_kernel() {
    int i = blockIdx.x * blockDim.x + threadIdx.x;
    if (i < HASH * TSZ) g_hist[i] = 0;
}

// ---------------- 1: kernel-row norms + global scale ------------------------
__global__ void norms_kernel(const float* __restrict__ w) {
    __shared__ float sn[256];
    int o = threadIdx.x;             // 256 threads == 256 kernel rows
    const float* row = w + o * KW2;
    float s = 0.f;
    for (int j = 0; j < KW2; j++) { float v = row[j]; s += v * v; }
    float nrm = sqrtf(s);
    g_norm[o] = nrm;
    sn[o] = nrm;
    __syncthreads();
    for (int st = 128; st > 0; st >>= 1) {
        if (o < st) sn[o] = fmaxf(sn[o], sn[o + st]);
        __syncthreads();
    }
    if (o == 0) g_scale = UBND / sn[0];
}

// ---------------- 2: bucket id of every kernel under every hash -------------
// one warp per (h, o) pair; 2048 warps total
__global__ void kbuckets_kernel(const float* __restrict__ w,
                                const float* __restrict__ a,
                                const float* __restrict__ b) {
    int wid  = (blockIdx.x * blockDim.x + threadIdx.x) >> 5;
    int lane = threadIdx.x & 31;
    if (wid >= HASH * OCH) return;
    int h = wid >> 8;        // /256
    int o = wid & 255;

    const float* ar = a + h * D_A;
    const float* wr = w + o * KW2;
    float s = 0.f;
    for (int j = lane; j < KW2; j += 32) s += ar[j] * wr[j];
    #pragma unroll
    for (int off = 16; off; off >>= 1) s += __shfl_down_sync(0xffffffffu, s, off);

    if (lane == 0) {
        float dot = g_scale * s;                 // a_flat . scaled_row
        float t = g_scale * g_norm[o];           // sn
        #pragma unroll 1
        for (int p = 0; p < MPOW; p++) {         // sn^(2^1) ... sn^(2^27)
            t = t * t;
            dot += ar[KW2 + p] * t;
        }
        float v  = floorf((dot + b[h]) / RADIUS);
        int   bk = (int)fabsf(fmodf(v, (float)TSZ));
        g_kbuckets[h * OCH + o] = bk;
    }
}

// ---------------- 3: vote — hash conv of padded input + histogram -----------
// tile 32x32 output px; 256 threads; each thread: 4 px (column of 4 rows),
// all 8 hash accumulators in registers.
#define VT 32
__global__ void vote_kernel(const float* __restrict__ x,
                            const float* __restrict__ a,
                            const float* __restrict__ b) {
    __shared__ float xs[4][VT + 2][36];       // 4-ch chunk, padded input tile
    __shared__ float ws[4][9][HASH];          // hash weights for this chunk
    __shared__ float sb[HASH];
    __shared__ int   shist[HASH * TSZ];

    int tid = threadIdx.x;
    int n   = blockIdx.z;
    int x0  = blockIdx.x * VT;
    int y0  = blockIdx.y * VT;

    for (int e = tid; e < HASH * TSZ; e += 256) shist[e] = 0;
    if (tid < HASH) sb[tid] = b[tid];

    int col = tid & 31;
    int rb  = (tid >> 5) << 2;

    float acc[HASH][4];
    #pragma unroll
    for (int h = 0; h < HASH; h++)
        #pragma unroll
        for (int p = 0; p < 4; p++) acc[h][p] = 0.f;

    // 67 channels (last 3 are constant 0.5 inside the image, 0 in padding),
    // processed as 17 chunks of 4 (68th channel is zero-padded).
    for (int c0 = 0; c0 < 68; c0 += 4) {
        __syncthreads();
        for (int e = tid; e < 4 * 34 * 34; e += 256) {
            int c   = e / (34 * 34);
            int rem = e % (34 * 34);
            int ry = rem / 34, rx = rem % 34;
            int cg = c0 + c;
            int gy = y0 - 1 + ry, gx = x0 - 1 + rx;
            float v = 0.f;
            if (cg < 67 && gy >= 0 && gy < HW && gx >= 0 && gx < HW)
                v = (cg < C_IN) ? x[((n * C_IN + cg) * HW + gy) * HW + gx] : 0.5f;
            xs[c][ry][rx] = v;
        }
        for (int e = tid; e < 4 * 9 * HASH; e += 256) {
            int h   = e % HASH;
            int rem = e / HASH;
            int c = rem / 9, khw = rem % 9;
            int cg = c0 + c;
            ws[c][khw][h] = (cg < 67) ? a[h * D_A + cg * 9 + khw] : 0.f;
        }
        __syncthreads();

        #pragma unroll
        for (int c = 0; c < 4; c++) {
            #pragma unroll
            for (int kh = 0; kh < 3; kh++) {
                #pragma unroll
                for (int kw = 0; kw < 3; kw++) {
                    float wv[HASH];
                    #pragma unroll
                    for (int h = 0; h < HASH; h++) wv[h] = ws[c][kh * 3 + kw][h];
                    float xv[4];
                    #pragma unroll
                    for (int p = 0; p < 4; p++) xv[p] = xs[c][rb + p + kh][col + kw];
                    #pragma unroll
                    for (int h = 0; h < HASH; h++)
                        #pragma unroll
                        for (int p = 0; p < 4; p++) acc[h][p] += wv[h] * xv[p];
                }
            }
        }
    }
    __syncthreads();

    #pragma unroll
    for (int h = 0; h < HASH; h++) {
        #pragma unroll
        for (int p = 0; p < 4; p++) {
            float v  = floorf((acc[h][p] + sb[h]) / RADIUS);
            int   bk = (int)fabsf(fmodf(v, (float)TSZ));
            atomicAdd(&shist[h * TSZ + bk], 1);
        }
    }
    __syncthreads();
    for (int e = tid; e < HASH * TSZ; e += 256) {
        int v = shist[e];
        if (v) atomicAdd(&g_hist[e], v);
    }
}

// ---------------- 4: argmax per hash (ties -> lowest index, like jnp) -------
__global__ void argmax_kernel() {
    int w    = threadIdx.x >> 5;   // 8 warps, one per hash
    int lane = threadIdx.x & 31;
    int best = -1, bidx = 0;
    for (int j = lane; j < TSZ; j += 32) {
        int c = g_hist[w * TSZ + j];
        if (c > best) { best = c; bidx = j; }   // strict > keeps lowest j
    }
    #pragma unroll
    for (int off = 16; off; off >>= 1) {
        int ob = __shfl_down_sync(0xffffffffu, best, off);
        int oi = __shfl_down_sync(0xffffffffu, bidx, off);
        if (ob > best || (ob == best && oi < bidx)) { best = ob; bidx = oi; }
    }
    if (lane == 0) g_voted[w] = bidx;
}

// ---------------- 5: active-channel mask -------------------------------------
__global__ void mask_kernel() {
    __shared__ int sv[HASH];
    if (threadIdx.x < HASH) sv[threadIdx.x] = g_voted[threadIdx.x];
    __syncthreads();
    int o = threadIdx.x;
    int m = 0;
    #pragma unroll
    for (int h = 0; h < HASH; h++) {
        int kb = g_kbuckets[h * OCH + o];
        #pragma unroll
        for (int j = 0; j < HASH; j++) m |= (kb == sv[j]);
    }
    g_mask[o] = m;
}

// ---------------- 6: main conv (FFMA-bound direct conv) ----------------------
// block: 16x16 px tile x 32 output channels; 256 threads.
// thread: 8 oc x 4 px (column) = 32 accumulators.
#define CT 16
__global__ void conv_kernel(const float* __restrict__ x,
                            const float* __restrict__ w,
                            float* __restrict__ out) {
    __shared__ float xs[8][CT + 2][20];   // row stride 20 -> conflict-free
    __shared__ float ws[8][9][32];
    __shared__ float smask[32];

    int tid = threadIdx.x;
    int z   = blockIdx.z;
    int ocg = z & 7;
    int n   = z >> 3;
    int ocbase = ocg * 32;
    int x0 = blockIdx.x * CT, y0 = blockIdx.y * CT;

    if (tid < 32) smask[tid] = g_mask[ocbase + tid] ? 1.f : 0.f;
    __syncthreads();

    bool any = false;
    #pragma unroll
    for (int i = 0; i < 32; i++) any |= (smask[i] != 0.f);

    int ocsub = tid >> 6;         // 0..3  -> oc group of 8
    int pxg   = tid & 63;
    int col   = pxg & 15;         // 0..15
    int rb    = (pxg >> 4) << 2;  // 0,4,8,12

    if (!any) {                   // whole oc-group inactive: exact zeros
        #pragma unroll
        for (int i = 0; i < 8; i++) {
            int oc = ocbase + ocsub * 8 + i;
            #pragma unroll
            for (int p = 0; p < 4; p++)
                out[((n * OCH + oc) * HW + y0 + rb + p) * HW + x0 + col] = 0.f;
        }
        return;
    }

    float acc[8][4];
    #pragma unroll
    for (int i = 0; i < 8; i++)
        #pragma unroll
        for (int p = 0; p < 4; p++) acc[i][p] = 0.f;

    for (int c0 = 0; c0 < C_IN; c0 += 8) {
        __syncthreads();
        for (int e = tid; e < 8 * 18 * 18; e += 256) {
            int c   = e / 324;
            int rem = e % 324;
            int ry = rem / 18, rx = rem % 18;
            int gy = y0 - 1 + ry, gx = x0 - 1 + rx;
            float v = 0.f;
            if (gy >= 0 && gy < HW && gx >= 0 && gx < HW)
                v = x[((n * C_IN + c0 + c) * HW + gy) * HW + gx];
            xs[c][ry][rx] = v;
        }
        for (int e = tid; e < 8 * 9 * 32; e += 256) {
            int oc  = e / 72;
            int rem = e % 72;
            int c = rem / 9, khw = rem % 9;
            ws[c][khw][oc] = w[(ocbase + oc) * KW2 + (c0 + c) * 9 + khw];
        }
        __syncthreads();

        #pragma unroll 2
        for (int c = 0; c < 8; c++) {
            #pragma unroll
            for (int kh = 0; kh < 3; kh++) {
                #pragma unroll
                for (int kw = 0; kw < 3; kw++) {
                    float wv[8];
                    #pragma unroll
                    for (int i = 0; i < 8; i++) wv[i] = ws[c][kh * 3 + kw][ocsub * 8 + i];
                    float xv[4];
                    #pragma unroll
                    for (int p = 0; p < 4; p++) xv[p] = xs[c][rb + p + kh][col + kw];
                    #pragma unroll
                    for (int i = 0; i < 8; i++)
                        #pragma unroll
                        for (int p = 0; p < 4; p++) acc[i][p] += wv[i] * xv[p];
                }
            }
        }
    }

    #pragma unroll
    for (int i = 0; i < 8; i++) {
        float m  = smask[ocsub * 8 + i];
        int   oc = ocbase + ocsub * 8 + i;
        #pragma unroll
        for (int p = 0; p < 4; p++)
            out[((n * OCH + oc) * HW + y0 + rb + p) * HW + x0 + col] = acc[i][p] * m;
    }
}

// ---------------- launch ------------------------------------------------------
extern "C" void kernel_launch(void* const* d_in, const int* in_sizes, int n_in,
                              void* d_out, int out_size) {
    const float* x = (const float*)d_in[0];   // [32,64,128,128]
    const float* w = (const float*)d_in[1];   // [256,64,3,3]
    const float* a = (const float*)d_in[2];   // [8,67,3,3]
    const float* b = (const float*)d_in[3];   // [8]
    float* out = (float*)d_out;               // [32,256,128,128]

    zero_hist_kernel<<<16, 256>>>();
    norms_kernel<<<1, 256>>>(w);
    kbuckets_kernel<<<256, 256>>>(w, a, b);
    vote_kernel<<<dim3(4, 4, NB), 256>>>(x, a, b);
    argmax_kernel<<<1, 256>>>();
    mask_kernel<<<1, 256>>>();
    conv_kernel<<<dim3(HW / CT, HW / CT, NB * 8), 256>>>(x, w, out);
}

// round 4
// speedup vs baseline: 1.0012x; 1.0003x over previous
#include <cuda_runtime.h>
#include <math.h>

// ---------------- problem constants (fixed by setup_inputs) ----------------
#define NB     32     // batch
#define C_IN   64     // input channels
#define HW     128    // spatial H = W
#define OCH    256    // output channels
#define HASH   8      // num hashes
#define D_A    603    // (64+3)*9
#define KW2    576    // 64*9
#define MPOW   27     // appended power dims (3*9)
#define TSZ    512    // table size
#define RADIUS 4.0f
#define UBND   0.99f

// ---------------- device scratch (no allocations allowed) ------------------
__device__ int   g_hist[HASH * TSZ];
__device__ float g_norm[OCH];
__device__ float g_scale;
__device__ int   g_kbuckets[HASH * OCH];
__device__ int   g_voted[HASH];
__device__ int   g_mask[OCH];

// ---------------- 0: zero the global histogram -----------------------------
__global__ void zero_hist_kernel() {
    int i = blockIdx.x * blockDim.x + threadIdx.x;
    if (i < HASH * TSZ) g_hist[i] = 0;
}

// ---------------- 1: kernel-row norms + global scale ------------------------
__global__ void norms_kernel(const float* __restrict__ w) {
    __shared__ float sn[256];
    int o = threadIdx.x;             // 256 threads == 256 kernel rows
    const float* row = w + o * KW2;
    float s = 0.f;
    for (int j = 0; j < KW2; j++) { float v = row[j]; s += v * v; }
    float nrm = sqrtf(s);
    g_norm[o] = nrm;
    sn[o] = nrm;
    __syncthreads();
    for (int st = 128; st > 0; st >>= 1) {
        if (o < st) sn[o] = fmaxf(sn[o], sn[o + st]);
        __syncthreads();
    }
    if (o == 0) g_scale = UBND / sn[0];
}

// ---------------- 2: bucket id of every kernel under every hash -------------
// one warp per (h, o) pair; 2048 warps total
__global__ void kbuckets_kernel(const float* __restrict__ w,
                                const float* __restrict__ a,
                                const float* __restrict__ b) {
    int wid  = (blockIdx.x * blockDim.x + threadIdx.x) >> 5;
    int lane = threadIdx.x & 31;
    if (wid >= HASH * OCH) return;
    int h = wid >> 8;        // /256
    int o = wid & 255;

    const float* ar = a + h * D_A;
    const float* wr = w + o * KW2;
    float s = 0.f;
    for (int j = lane; j < KW2; j += 32) s += ar[j] * wr[j];
    #pragma unroll
    for (int off = 16; off; off >>= 1) s += __shfl_down_sync(0xffffffffu, s, off);

    if (lane == 0) {
        float dot = g_scale * s;                 // a_flat . scaled_row
        float t = g_scale * g_norm[o];           // sn
        #pragma unroll 1
        for (int p = 0; p < MPOW; p++) {         // sn^(2^1) ... sn^(2^27)
            t = t * t;
            dot += ar[KW2 + p] * t;
        }
        float v  = floorf((dot + b[h]) / RADIUS);
        int   bk = (int)fabsf(fmodf(v, (float)TSZ));
        g_kbuckets[h * OCH + o] = bk;
    }
}

// ---------------- 3: vote — hash conv of padded input + histogram -----------
// tile 32x32 output px; 256 threads; each thread: 4 px (column of 4 rows),
// all 8 hash accumulators in registers.
#define VT 32
__global__ void vote_kernel(const float* __restrict__ x,
                            const float* __restrict__ a,
                            const float* __restrict__ b) {
    __shared__ float xs[4][VT + 2][36];       // 4-ch chunk, padded input tile
    __shared__ float ws[4][9][HASH];          // hash weights for this chunk
    __shared__ float sb[HASH];
    __shared__ int   shist[HASH * TSZ];

    int tid = threadIdx.x;
    int n   = blockIdx.z;
    int x0  = blockIdx.x * VT;
    int y0  = blockIdx.y * VT;

    for (int e = tid; e < HASH * TSZ; e += 256) shist[e] = 0;
    if (tid < HASH) sb[tid] = b[tid];

    int col = tid & 31;
    int rb  = (tid >> 5) << 2;

    float acc[HASH][4];
    #pragma unroll
    for (int h = 0; h < HASH; h++)
        #pragma unroll
        for (int p = 0; p < 4; p++) acc[h][p] = 0.f;

    // 67 channels (last 3 are constant 0.5 inside the image, 0 in padding),
    // processed as 17 chunks of 4 (68th channel is zero-padded).
    for (int c0 = 0; c0 < 68; c0 += 4) {
        __syncthreads();
        for (int e = tid; e < 4 * 34 * 34; e += 256) {
            int c   = e / (34 * 34);
            int rem = e % (34 * 34);
            int ry = rem / 34, rx = rem % 34;
            int cg = c0 + c;
            int gy = y0 - 1 + ry, gx = x0 - 1 + rx;
            float v = 0.f;
            if (cg < 67 && gy >= 0 && gy < HW && gx >= 0 && gx < HW)
                v = (cg < C_IN) ? x[((n * C_IN + cg) * HW + gy) * HW + gx] : 0.5f;
            xs[c][ry][rx] = v;
        }
        for (int e = tid; e < 4 * 9 * HASH; e += 256) {
            int h   = e % HASH;
            int rem = e / HASH;
            int c = rem / 9, khw = rem % 9;
            int cg = c0 + c;
            ws[c][khw][h] = (cg < 67) ? a[h * D_A + cg * 9 + khw] : 0.f;
        }
        __syncthreads();

        #pragma unroll
        for (int c = 0; c < 4; c++) {
            #pragma unroll
            for (int kh = 0; kh < 3; kh++) {
                #pragma unroll
                for (int kw = 0; kw < 3; kw++) {
                    float wv[HASH];
                    #pragma unroll
                    for (int h = 0; h < HASH; h++) wv[h] = ws[c][kh * 3 + kw][h];
                    float xv[4];
                    #pragma unroll
                    for (int p = 0; p < 4; p++) xv[p] = xs[c][rb + p + kh][col + kw];
                    #pragma unroll
                    for (int h = 0; h < HASH; h++)
                        #pragma unroll
                        for (int p = 0; p < 4; p++) acc[h][p] += wv[h] * xv[p];
                }
            }
        }
    }
    __syncthreads();

    #pragma unroll
    for (int h = 0; h < HASH; h++) {
        #pragma unroll
        for (int p = 0; p < 4; p++) {
            float v  = floorf((acc[h][p] + sb[h]) / RADIUS);
            int   bk = (int)fabsf(fmodf(v, (float)TSZ));
            atomicAdd(&shist[h * TSZ + bk], 1);
        }
    }
    __syncthreads();
    for (int e = tid; e < HASH * TSZ; e += 256) {
        int v = shist[e];
        if (v) atomicAdd(&g_hist[e], v);
    }
}

// ---------------- 4: argmax per hash (ties -> lowest index, like jnp) -------
__global__ void argmax_kernel() {
    int w    = threadIdx.x >> 5;   // 8 warps, one per hash
    int lane = threadIdx.x & 31;
    int best = -1, bidx = 0;
    for (int j = lane; j < TSZ; j += 32) {
        int c = g_hist[w * TSZ + j];
        if (c > best) { best = c; bidx = j; }   // strict > keeps lowest j
    }
    #pragma unroll
    for (int off = 16; off; off >>= 1) {
        int ob = __shfl_down_sync(0xffffffffu, best, off);
        int oi = __shfl_down_sync(0xffffffffu, bidx, off);
        if (ob > best || (ob == best && oi < bidx)) { best = ob; bidx = oi; }
    }
    if (lane == 0) g_voted[w] = bidx;
}

// ---------------- 5: active-channel mask -------------------------------------
__global__ void mask_kernel() {
    __shared__ int sv[HASH];
    if (threadIdx.x < HASH) sv[threadIdx.x] = g_voted[threadIdx.x];
    __syncthreads();
    int o = threadIdx.x;
    int m = 0;
    #pragma unroll
    for (int h = 0; h < HASH; h++) {
        int kb = g_kbuckets[h * OCH + o];
        #pragma unroll
        for (int j = 0; j < HASH; j++) m |= (kb == sv[j]);
    }
    g_mask[o] = m;
}

// ---------------- 6: main conv (FFMA-bound direct conv) ----------------------
// block: 16x16 px tile x 32 output channels; 256 threads.
// thread: 8 oc x 4 px (column) = 32 accumulators.
#define CT 16
__global__ void conv_kernel(const float* __restrict__ x,
                            const float* __restrict__ w,
                            float* __restrict__ out) {
    __shared__ float xs[8][CT + 2][20];   // row stride 20 -> conflict-free
    __shared__ float ws[8][9][32];
    __shared__ float smask[32];

    int tid = threadIdx.x;
    int z   = blockIdx.z;
    int ocg = z & 7;
    int n   = z >> 3;
    int ocbase = ocg * 32;
    int x0 = blockIdx.x * CT, y0 = blockIdx.y * CT;

    if (tid < 32) smask[tid] = g_mask[ocbase + tid] ? 1.f : 0.f;
    __syncthreads();

    bool any = false;
    #pragma unroll
    for (int i = 0; i < 32; i++) any |= (smask[i] != 0.f);

    int ocsub = tid >> 6;         // 0..3  -> oc group of 8
    int pxg   = tid & 63;
    int col   = pxg & 15;         // 0..15
    int rb    = (pxg >> 4) << 2;  // 0,4,8,12

    if (!any) {                   // whole oc-group inactive: exact zeros
        #pragma unroll
        for (int i = 0; i < 8; i++) {
            int oc = ocbase + ocsub * 8 + i;
            #pragma unroll
            for (int p = 0; p < 4; p++)
                out[((n * OCH + oc) * HW + y0 + rb + p) * HW + x0 + col] = 0.f;
        }
        return;
    }

    float acc[8][4];
    #pragma unroll
    for (int i = 0; i < 8; i++)
        #pragma unroll
        for (int p = 0; p < 4; p++) acc[i][p] = 0.f;

    for (int c0 = 0; c0 < C_IN; c0 += 8) {
        __syncthreads();
        for (int e = tid; e < 8 * 18 * 18; e += 256) {
            int c   = e / 324;
            int rem = e % 324;
            int ry = rem / 18, rx = rem % 18;
            int gy = y0 - 1 + ry, gx = x0 - 1 + rx;
            float v = 0.f;
            if (gy >= 0 && gy < HW && gx >= 0 && gx < HW)
                v = x[((n * C_IN + c0 + c) * HW + gy) * HW + gx];
            xs[c][ry][rx] = v;
        }
        for (int e = tid; e < 8 * 9 * 32; e += 256) {
            int oc  = e / 72;
            int rem = e % 72;
            int c = rem / 9, khw = rem % 9;
            ws[c][khw][oc] = w[(ocbase + oc) * KW2 + (c0 + c) * 9 + khw];
        }
        __syncthreads();

        #pragma unroll 2
        for (int c = 0; c < 8; c++) {
            #pragma unroll
            for (int kh = 0; kh < 3; kh++) {
                #pragma unroll
                for (int kw = 0; kw < 3; kw++) {
                    float wv[8];
                    #pragma unroll
                    for (int i = 0; i < 8; i++) wv[i] = ws[c][kh * 3 + kw][ocsub * 8 + i];
                    float xv[4];
                    #pragma unroll
                    for (int p = 0; p < 4; p++) xv[p] = xs[c][rb + p + kh][col + kw];
                    #pragma unroll
                    for (int i = 0; i < 8; i++)
                        #pragma unroll
                        for (int p = 0; p < 4; p++) acc[i][p] += wv[i] * xv[p];
                }
            }
        }
    }

    #pragma unroll
    for (int i = 0; i < 8; i++) {
        float m  = smask[ocsub * 8 + i];
        int   oc = ocbase + ocsub * 8 + i;
        #pragma unroll
        for (int p = 0; p < 4; p++)
            out[((n * OCH + oc) * HW + y0 + rb + p) * HW + x0 + col] = acc[i][p] * m;
    }
}

// ---------------- launch ------------------------------------------------------
extern "C" void kernel_launch(void* const* d_in, const int* in_sizes, int n_in,
                              void* d_out, int out_size) {
    const float* x = (const float*)d_in[0];   // [32,64,128,128]
    const float* w = (const float*)d_in[1];   // [256,64,3,3]
    const float* a = (const float*)d_in[2];   // [8,67,3,3]
    const float* b = (const float*)d_in[3];   // [8]
    float* out = (float*)d_out;               // [32,256,128,128]

    zero_hist_kernel<<<16, 256>>>();
    norms_kernel<<<1, 256>>>(w);
    kbuckets_kernel<<<256, 256>>>(w, a, b);
    vote_kernel<<<dim3(4, 4, NB), 256>>>(x, a, b);
    argmax_kernel<<<1, 256>>>();
    mask_kernel<<<1, 256>>>();
    conv_kernel<<<dim3(HW / CT, HW / CT, NB * 8), 256>>>(x, w, out);
}

// round 6
// speedup vs baseline: 2.4239x; 2.4209x over previous
#include <cuda_runtime.h>
#include <cuda_bf16.h>
#include <math.h>
#include <stdint.h>

// ---------------- problem constants ----------------
#define NB     32
#define C_IN   64
#define HW     128
#define OCH    256
#define HASH   8
#define D_A    603
#define KW2    576
#define MPOW   27
#define TSZ    512
#define RADIUS 4.0f
#define UBND   0.99f

// ---------------- device scratch ----------------
__device__ int   g_hist[HASH * TSZ];
__device__ float g_norm[OCH];
__device__ float g_scale;
__device__ int   g_kbuckets[HASH * OCH];
__device__ int   g_voted[HASH];
__device__ int   g_mask[OCH];
// permuted bf16 weights: [tap 9][prec 2][oc 256][128 B]  (see cslot perm)
__device__ uint4 g_wq[36864];   // 589,824 B

// ---------------- helpers ----------------
__device__ __forceinline__ uint32_t smem_u32(const void* p) {
    uint32_t a;
    asm("{ .reg .u64 t; cvta.to.shared.u64 t, %1; cvt.u32.u64 %0, t; }" : "=r"(a) : "l"(p));
    return a;
}
// channel -> byte offset inside a 128B packed row (pair-permuted for mma frags)
__device__ __forceinline__ int cslot(int c) {
    int gg = c >> 4, r = c & 15, q = r >> 1, odd = r & 1;
    int slot = (q < 4) ? (q << 1) : (((q - 4) << 1) | 1);
    return gg * 32 + slot * 4 + odd * 2;
}
__device__ __forceinline__ void mma16816(float* c, uint32_t a0, uint32_t a1,
                                         uint32_t a2, uint32_t a3,
                                         uint32_t b0, uint32_t b1) {
    asm volatile(
        "mma.sync.aligned.m16n8k16.row.col.f32.bf16.bf16.f32 "
        "{%0,%1,%2,%3}, {%4,%5,%6,%7}, {%8,%9}, {%0,%1,%2,%3};"
        : "+f"(c[0]), "+f"(c[1]), "+f"(c[2]), "+f"(c[3])
        : "r"(a0), "r"(a1), "r"(a2), "r"(a3), "r"(b0), "r"(b1));
}
__device__ __forceinline__ void cp_async16(uint32_t dst, const void* src) {
    asm volatile("{ .reg .u64 gp; cvta.to.global.u64 gp, %1; "
                 "cp.async.cg.shared.global [%0], [gp], 16; }"
                 :: "r"(dst), "l"(src) : "memory");
}
#define CP_COMMIT() asm volatile("cp.async.commit_group;" ::: "memory")
#define CP_WAIT0()  asm volatile("cp.async.wait_group 0;" ::: "memory")

// ---------------- 0: zero hist ----------------
__global__ void zero_hist_kernel() {
    int i = blockIdx.x * blockDim.x + threadIdx.x;
    if (i < HASH * TSZ) g_hist[i] = 0;
}

// ---------------- 1: norms + scale ----------------
__global__ void norms_kernel(const float* __restrict__ w) {
    __shared__ float sn[256];
    int o = threadIdx.x;
    const float* row = w + o * KW2;
    float s = 0.f;
    for (int j = 0; j < KW2; j++) { float v = row[j]; s += v * v; }
    float nrm = sqrtf(s);
    g_norm[o] = nrm;
    sn[o] = nrm;
    __syncthreads();
    for (int st = 128; st > 0; st >>= 1) {
        if (o < st) sn[o] = fmaxf(sn[o], sn[o + st]);
        __syncthreads();
    }
    if (o == 0) g_scale = UBND / sn[0];
}

// ---------------- 2: kernel buckets ----------------
__global__ void kbuckets_kernel(const float* __restrict__ w,
                                const float* __restrict__ a,
                                const float* __restrict__ b) {
    int wid  = (blockIdx.x * blockDim.x + threadIdx.x) >> 5;
    int lane = threadIdx.x & 31;
    if (wid >= HASH * OCH) return;
    int h = wid >> 8, o = wid & 255;
    const float* ar = a + h * D_A;
    const float* wr = w + o * KW2;
    float s = 0.f;
    for (int j = lane; j < KW2; j += 32) s += ar[j] * wr[j];
    #pragma unroll
    for (int off = 16; off; off >>= 1) s += __shfl_down_sync(0xffffffffu, s, off);
    if (lane == 0) {
        float dot = g_scale * s;
        float t = g_scale * g_norm[o];
        #pragma unroll 1
        for (int p = 0; p < MPOW; p++) { t = t * t; dot += ar[KW2 + p] * t; }
        float v = floorf((dot + b[h]) / RADIUS);
        g_kbuckets[h * OCH + o] = (int)fabsf(fmodf(v, (float)TSZ));
    }
}

// ---------------- 2b: weight prep (fp32 -> permuted bf16 hi/lo) -------------
__global__ void wprep_kernel(const float* __restrict__ w) {
    int i = blockIdx.x * blockDim.x + threadIdx.x;
    if (i >= OCH * KW2) return;
    int o = i / KW2, rem = i % KW2;
    int c = rem / 9, t = rem % 9;          // k = c*9 + t,  t = kh*3+kw
    float v = w[i];
    __nv_bfloat16 hi = __float2bfloat16(v);
    __nv_bfloat16 lo = __float2bfloat16(v - __bfloat162float(hi));
    char* base = (char*)g_wq;
    int co = cslot(c);
    *(__nv_bfloat16*)(base + ((size_t)(t * 2 + 0) * 256 + o) * 128 + co) = hi;
    *(__nv_bfloat16*)(base + ((size_t)(t * 2 + 1) * 256 + o) * 128 + co) = lo;
}

// ---------------- 3: vote (16x16 tiles) ----------------
#define VT 16
__global__ void vote_kernel(const float* __restrict__ x,
                            const float* __restrict__ a,
                            const float* __restrict__ b) {
    __shared__ float xs[4][VT + 2][20];
    __shared__ float ws[4][9][HASH];
    __shared__ float sb[HASH];
    __shared__ int   shist[HASH * TSZ];

    int tid = threadIdx.x;
    int n = blockIdx.z, x0 = blockIdx.x * VT, y0 = blockIdx.y * VT;

    for (int e = tid; e < HASH * TSZ; e += 256) shist[e] = 0;
    if (tid < HASH) sb[tid] = b[tid];

    int px = tid & 15, py = tid >> 4;
    float acc[HASH];
    #pragma unroll
    for (int h = 0; h < HASH; h++) acc[h] = 0.f;

    for (int c0 = 0; c0 < 68; c0 += 4) {
        __syncthreads();
        for (int e = tid; e < 4 * 18 * 18; e += 256) {
            int c = e / 324, rem = e % 324;
            int ry = rem / 18, rx = rem % 18;
            int cg = c0 + c;
            int gy = y0 - 1 + ry, gx = x0 - 1 + rx;
            float v = 0.f;
            if (cg < 67 && gy >= 0 && gy < HW && gx >= 0 && gx < HW)
                v = (cg < C_IN) ? x[((n * C_IN + cg) * HW + gy) * HW + gx] : 0.5f;
            xs[c][ry][rx] = v;
        }
        for (int e = tid; e < 4 * 9 * HASH; e += 256) {
            int h = e % HASH, rem = e / HASH;
            int c = rem / 9, khw = rem % 9;
            int cg = c0 + c;
            ws[c][khw][h] = (cg < 67) ? a[h * D_A + cg * 9 + khw] : 0.f;
        }
        __syncthreads();
        #pragma unroll
        for (int c = 0; c < 4; c++)
            #pragma unroll
            for (int kh = 0; kh < 3; kh++)
                #pragma unroll
                for (int kw = 0; kw < 3; kw++) {
                    float xv = xs[c][py + kh][px + kw];
                    #pragma unroll
                    for (int h = 0; h < HASH; h++) acc[h] += ws[c][kh * 3 + kw][h] * xv;
                }
    }
    __syncthreads();
    #pragma unroll
    for (int h = 0; h < HASH; h++) {
        float v = floorf((acc[h] + sb[h]) / RADIUS);
        int bk = (int)fabsf(fmodf(v, (float)TSZ));
        atomicAdd(&shist[h * TSZ + bk], 1);
    }
    __syncthreads();
    for (int e = tid; e < HASH * TSZ; e += 256) {
        int v = shist[e];
        if (v) atomicAdd(&g_hist[e], v);
    }
}

// ---------------- 4: argmax ----------------
__global__ void argmax_kernel() {
    int w = threadIdx.x >> 5, lane = threadIdx.x & 31;
    int best = -1, bidx = 0;
    for (int j = lane; j < TSZ; j += 32) {
        int c = g_hist[w * TSZ + j];
        if (c > best) { best = c; bidx = j; }
    }
    #pragma unroll
    for (int off = 16; off; off >>= 1) {
        int ob = __shfl_down_sync(0xffffffffu, best, off);
        int oi = __shfl_down_sync(0xffffffffu, bidx, off);
        if (ob > best || (ob == best && oi < bidx)) { best = ob; bidx = oi; }
    }
    if (lane == 0) g_voted[w] = bidx;
}

// ---------------- 5: mask ----------------
__global__ void mask_kernel() {
    __shared__ int sv[HASH];
    if (threadIdx.x < HASH) sv[threadIdx.x] = g_voted[threadIdx.x];
    __syncthreads();
    int o = threadIdx.x, m = 0;
    #pragma unroll
    for (int h = 0; h < HASH; h++) {
        int kb = g_kbuckets[h * OCH + o];
        #pragma unroll
        for (int j = 0; j < HASH; j++) m |= (kb == sv[j]);
    }
    g_mask[o] = m;
}

// ---------------- 6: warp-MMA implicit-GEMM conv -----------------------------
// CTA 512 thr: M=128 oc (ocg half), N=256 px (2 rows), K=576.
// Warp grid 4(M)x4(N); warp tile 32x64. bf16 hi/lo split: 3 MMAs / k16 chunk.
// T-slab: x rows y0-1..y0+2 as bf16 hi/lo, layout [rr][xi(130)][c-packed 128B],
// row pitch 144B. B fragments read directly from T (per-tap shifted window).
#define T_OFF   512
#define T_PER   74880         // 4*130*144
#define A_OFF   150272        // 512 + 2*T_PER
#define A_PREC  18432         // 128*144
#define A_BUF   36864
#define SMEM_CONV 224000

__device__ __forceinline__ void copyA_tap(uint32_t sb, int t, int buf, int ocg, int tid) {
    const char* gb = (const char*)g_wq;
    #pragma unroll
    for (int q = 0; q < 4; q++) {
        int e = q * 512 + tid;            // 0..2047
        int p = e >> 10, idx = e & 1023;
        int oc = idx >> 3, j = idx & 7;
        const char* src = gb + ((size_t)(t * 2 + p) * 256 + ocg * 128 + oc) * 128 + j * 16;
        uint32_t dst = sb + A_OFF + buf * A_BUF + p * A_PREC + oc * 144 + j * 16;
        cp_async16(dst, src);
    }
}

__global__ void __launch_bounds__(512, 1)
conv_mma_kernel(const float* __restrict__ x, float* __restrict__ out) {
    extern __shared__ __align__(16) char smem[];
    uint32_t sb = smem_u32(smem);
    int tid = threadIdx.x, wid = tid >> 5, lane = tid & 31;
    int ocg = blockIdx.x, rp = blockIdx.y, img = blockIdx.z;
    int y0 = rp * 2;

    float* smask = (float*)smem;
    if (tid < 128) smask[tid] = g_mask[ocg * 128 + tid] ? 1.f : 0.f;

    // prefetch A tap 0
    copyA_tap(sb, 0, 0, ocg, tid);
    CP_COMMIT();

    // zero T (padding cols + OOB rows stay zero)
    {
        uint4 z = {0, 0, 0, 0};
        uint4* tz = (uint4*)(smem + T_OFF);
        for (int e = tid; e < 2 * T_PER / 16; e += 512) tz[e] = z;
    }
    __syncthreads();

    // build T interior
    for (int e = tid; e < 4 * C_IN * HW; e += 512) {
        int rr = e >> 13, rem = e & 8191;
        int c = rem >> 7, xc = rem & 127;
        int y = y0 - 1 + rr;
        if (y >= 0 && y < HW) {
            float v = x[((img * C_IN + c) * HW + y) * HW + xc];
            __nv_bfloat16 hi = __float2bfloat16(v);
            __nv_bfloat16 lo = __float2bfloat16(v - __bfloat162float(hi));
            int off = (rr * 130 + xc + 1) * 144 + cslot(c);
            *(__nv_bfloat16*)(smem + T_OFF + off)         = hi;
            *(__nv_bfloat16*)(smem + T_OFF + T_PER + off) = lo;
        }
    }
    __syncthreads();

    int m0   = (wid & 3) * 32;
    int n0w  = (wid >> 2) * 64;
    int yrel = n0w >> 7;
    int x0w  = n0w & 127;
    int lr   = lane >> 2;        // 0..7
    int lj   = lane & 3;         // 0..3

    float acc[2][8][4];
    #pragma unroll
    for (int mt = 0; mt < 2; mt++)
        #pragma unroll
        for (int nt = 0; nt < 8; nt++)
            #pragma unroll
            for (int q = 0; q < 4; q++) acc[mt][nt][q] = 0.f;

    for (int t = 0; t < 9; t++) {
        int kh = t / 3, kw = t % 3, buf = t & 1;
        CP_WAIT0();
        __syncthreads();
        if (t < 8) { copyA_tap(sb, t + 1, buf ^ 1, ocg, tid); CP_COMMIT(); }

        const char* Ah = smem + A_OFF + buf * A_BUF;
        const char* Al = Ah + A_PREC;
        int rr = yrel + kh;
        const char* Tb = smem + T_OFF + (rr * 130 + kw) * 144;

        #pragma unroll
        for (int ks = 0; ks < 4; ks++) {
            int fo = ks * 32 + lj * 8;
            uint32_t ah[2][4], al[2][4];
            #pragma unroll
            for (int mt = 0; mt < 2; mt++) {
                int r0 = (m0 + mt * 16 + lr) * 144 + fo;
                int r8 = r0 + 8 * 144;
                ah[mt][0] = *(const uint32_t*)(Ah + r0);
                ah[mt][1] = *(const uint32_t*)(Ah + r8);
                ah[mt][2] = *(const uint32_t*)(Ah + r0 + 4);
                ah[mt][3] = *(const uint32_t*)(Ah + r8 + 4);
                al[mt][0] = *(const uint32_t*)(Al + r0);
                al[mt][1] = *(const uint32_t*)(Al + r8);
                al[mt][2] = *(const uint32_t*)(Al + r0 + 4);
                al[mt][3] = *(const uint32_t*)(Al + r8 + 4);
            }
            #pragma unroll
            for (int nt = 0; nt < 8; nt++) {
                int xo = (x0w + nt * 8 + lr) * 144 + fo;
                uint32_t bh0 = *(const uint32_t*)(Tb + xo);
                uint32_t bh1 = *(const uint32_t*)(Tb + xo + 4);
                uint32_t bl0 = *(const uint32_t*)(Tb + T_PER + xo);
                uint32_t bl1 = *(const uint32_t*)(Tb + T_PER + xo + 4);
                mma16816(acc[0][nt], ah[0][0], ah[0][1], ah[0][2], ah[0][3], bh0, bh1);
                mma16816(acc[1][nt], ah[1][0], ah[1][1], ah[1][2], ah[1][3], bh0, bh1);
                mma16816(acc[0][nt], ah[0][0], ah[0][1], ah[0][2], ah[0][3], bl0, bl1);
                mma16816(acc[1][nt], ah[1][0], ah[1][1], ah[1][2], ah[1][3], bl0, bl1);
                mma16816(acc[0][nt], al[0][0], al[0][1], al[0][2], al[0][3], bh0, bh1);
                mma16816(acc[1][nt], al[1][0], al[1][1], al[1][2], al[1][3], bh0, bh1);
            }
        }
    }

    // epilogue: masked stores
    int y = y0 + yrel;
    #pragma unroll
    for (int mt = 0; mt < 2; mt++) {
        int mrow = m0 + mt * 16 + lr;
        float mk0 = smask[mrow];
        float mk1 = smask[mrow + 8];
        int oc0 = ocg * 128 + mrow;
        size_t b0 = ((size_t)(img * OCH + oc0) * HW + y) * HW;
        size_t b1 = b0 + (size_t)8 * HW * HW;
        #pragma unroll
        for (int nt = 0; nt < 8; nt++) {
            int xcol = x0w + nt * 8 + lj * 2;
            float2 v0 = { acc[mt][nt][0] * mk0, acc[mt][nt][1] * mk0 };
            float2 v1 = { acc[mt][nt][2] * mk1, acc[mt][nt][3] * mk1 };
            *(float2*)(out + b0 + xcol) = v0;
            *(float2*)(out + b1 + xcol) = v1;
        }
    }
}

// ---------------- launch ----------------
extern "C" void kernel_launch(void* const* d_in, const int* in_sizes, int n_in,
                              void* d_out, int out_size) {
    const float* x = (const float*)d_in[0];   // [32,64,128,128]
    const float* w = (const float*)d_in[1];   // [256,64,3,3]
    const float* a = (const float*)d_in[2];   // [8,67,3,3]
    const float* b = (const float*)d_in[3];   // [8]
    float* out = (float*)d_out;               // [32,256,128,128]

    cudaFuncSetAttribute(conv_mma_kernel,
                         cudaFuncAttributeMaxDynamicSharedMemorySize, SMEM_CONV);

    zero_hist_kernel<<<16, 256>>>();
    norms_kernel<<<1, 256>>>(w);
    kbuckets_kernel<<<256, 256>>>(w, a, b);
    wprep_kernel<<<576, 256>>>(w);
    vote_kernel<<<dim3(8, 8, NB), 256>>>(x, a, b);
    argmax_kernel<<<1, 256>>>();
    mask_kernel<<<1, 256>>>();
    conv_mma_kernel<<<dim3(2, 64, NB), 512, SMEM_CONV>>>(x, out);
}

// round 7
// speedup vs baseline: 4.0682x; 1.6784x over previous
#include <cuda_runtime.h>
#include <cuda_fp16.h>
#include <math.h>
#include <stdint.h>

// ---------------- problem constants ----------------
#define NB     32
#define C_IN   64
#define HW     128
#define OCH    256
#define HASH   8
#define D_A    603
#define KW2    576
#define MPOW   27
#define TSZ    512
#define RADIUS 4.0f
#define UBND   0.99f

// ---------------- device scratch ----------------
__device__ int   g_hist[HASH * TSZ];
__device__ float g_norm[OCH];
__device__ float g_scale;
__device__ int   g_kbuckets[HASH * OCH];
__device__ int   g_voted[HASH];
__device__ int   g_mask[OCH];
// permuted fp16 weights: [tap 9][oc 256][128 B]  (see cslot perm)
__device__ uint4 g_wq[18432];   // 294,912 B

// ---------------- helpers ----------------
__device__ __forceinline__ uint32_t smem_u32(const void* p) {
    uint32_t a;
    asm("{ .reg .u64 t; cvta.to.shared.u64 t, %1; cvt.u32.u64 %0, t; }" : "=r"(a) : "l"(p));
    return a;
}
// channel -> byte offset inside a 128B packed row (pair-permuted for mma frags)
__device__ __forceinline__ int cslot(int c) {
    int gg = c >> 4, r = c & 15, q = r >> 1, odd = r & 1;
    int slot = (q < 4) ? (q << 1) : (((q - 4) << 1) | 1);
    return gg * 32 + slot * 4 + odd * 2;
}
__device__ __forceinline__ void mma16816(float* c, uint32_t a0, uint32_t a1,
                                         uint32_t a2, uint32_t a3,
                                         uint32_t b0, uint32_t b1) {
    asm volatile(
        "mma.sync.aligned.m16n8k16.row.col.f32.f16.f16.f32 "
        "{%0,%1,%2,%3}, {%4,%5,%6,%7}, {%8,%9}, {%0,%1,%2,%3};"
        : "+f"(c[0]), "+f"(c[1]), "+f"(c[2]), "+f"(c[3])
        : "r"(a0), "r"(a1), "r"(a2), "r"(a3), "r"(b0), "r"(b1));
}
__device__ __forceinline__ void cp_async16(uint32_t dst, const void* src) {
    asm volatile("{ .reg .u64 gp; cvta.to.global.u64 gp, %1; "
                 "cp.async.cg.shared.global [%0], [gp], 16; }"
                 :: "r"(dst), "l"(src) : "memory");
}
#define CP_COMMIT() asm volatile("cp.async.commit_group;" ::: "memory")
#define CP_WAIT0()  asm volatile("cp.async.wait_group 0;" ::: "memory")

// ---------------- 0: zero hist ----------------
__global__ void zero_hist_kernel() {
    int i = blockIdx.x * blockDim.x + threadIdx.x;
    if (i < HASH * TSZ) g_hist[i] = 0;
}

// ---------------- 1: norms + scale ----------------
__global__ void norms_kernel(const float* __restrict__ w) {
    __shared__ float sn[256];
    int o = threadIdx.x;
    const float* row = w + o * KW2;
    float s = 0.f;
    for (int j = 0; j < KW2; j++) { float v = row[j]; s += v * v; }
    float nrm = sqrtf(s);
    g_norm[o] = nrm;
    sn[o] = nrm;
    __syncthreads();
    for (int st = 128; st > 0; st >>= 1) {
        if (o < st) sn[o] = fmaxf(sn[o], sn[o + st]);
        __syncthreads();
    }
    if (o == 0) g_scale = UBND / sn[0];
}

// ---------------- 2: kernel buckets ----------------
__global__ void kbuckets_kernel(const float* __restrict__ w,
                                const float* __restrict__ a,
                                const float* __restrict__ b) {
    int wid  = (blockIdx.x * blockDim.x + threadIdx.x) >> 5;
    int lane = threadIdx.x & 31;
    if (wid >= HASH * OCH) return;
    int h = wid >> 8, o = wid & 255;
    const float* ar = a + h * D_A;
    const float* wr = w + o * KW2;
    float s = 0.f;
    for (int j = lane; j < KW2; j += 32) s += ar[j] * wr[j];
    #pragma unroll
    for (int off = 16; off; off >>= 1) s += __shfl_down_sync(0xffffffffu, s, off);
    if (lane == 0) {
        float dot = g_scale * s;
        float t = g_scale * g_norm[o];
        #pragma unroll 1
        for (int p = 0; p < MPOW; p++) { t = t * t; dot += ar[KW2 + p] * t; }
        float v = floorf((dot + b[h]) / RADIUS);
        g_kbuckets[h * OCH + o] = (int)fabsf(fmodf(v, (float)TSZ));
    }
}

// ---------------- 2b: weight prep (fp32 -> permuted fp16) -------------------
__global__ void wprep_kernel(const float* __restrict__ w) {
    int i = blockIdx.x * blockDim.x + threadIdx.x;
    if (i >= OCH * KW2) return;
    int o = i / KW2, rem = i % KW2;
    int c = rem / 9, t = rem % 9;          // k = c*9 + t,  t = kh*3+kw
    float v = w[i];
    char* base = (char*)g_wq;
    *(__half*)(base + ((size_t)t * 256 + o) * 128 + cslot(c)) = __float2half(v);
}

// ---------------- 3: vote (16x16 tiles) ----------------
#define VT 16
__global__ void vote_kernel(const float* __restrict__ x,
                            const float* __restrict__ a,
                            const float* __restrict__ b) {
    __shared__ float xs[4][VT + 2][20];
    __shared__ float ws[4][9][HASH];
    __shared__ float sb[HASH];
    __shared__ int   shist[HASH * TSZ];

    int tid = threadIdx.x;
    int n = blockIdx.z, x0 = blockIdx.x * VT, y0 = blockIdx.y * VT;

    for (int e = tid; e < HASH * TSZ; e += 256) shist[e] = 0;
    if (tid < HASH) sb[tid] = b[tid];

    int px = tid & 15, py = tid >> 4;
    float acc[HASH];
    #pragma unroll
    for (int h = 0; h < HASH; h++) acc[h] = 0.f;

    for (int c0 = 0; c0 < 68; c0 += 4) {
        __syncthreads();
        for (int e = tid; e < 4 * 18 * 18; e += 256) {
            int c = e / 324, rem = e % 324;
            int ry = rem / 18, rx = rem % 18;
            int cg = c0 + c;
            int gy = y0 - 1 + ry, gx = x0 - 1 + rx;
            float v = 0.f;
            if (cg < 67 && gy >= 0 && gy < HW && gx >= 0 && gx < HW)
                v = (cg < C_IN) ? x[((n * C_IN + cg) * HW + gy) * HW + gx] : 0.5f;
            xs[c][ry][rx] = v;
        }
        for (int e = tid; e < 4 * 9 * HASH; e += 256) {
            int h = e % HASH, rem = e / HASH;
            int c = rem / 9, khw = rem % 9;
            int cg = c0 + c;
            ws[c][khw][h] = (cg < 67) ? a[h * D_A + cg * 9 + khw] : 0.f;
        }
        __syncthreads();
        #pragma unroll
        for (int c = 0; c < 4; c++)
            #pragma unroll
            for (int kh = 0; kh < 3; kh++)
                #pragma unroll
                for (int kw = 0; kw < 3; kw++) {
                    float xv = xs[c][py + kh][px + kw];
                    #pragma unroll
                    for (int h = 0; h < HASH; h++) acc[h] += ws[c][kh * 3 + kw][h] * xv;
                }
    }
    __syncthreads();
    #pragma unroll
    for (int h = 0; h < HASH; h++) {
        float v = floorf((acc[h] + sb[h]) / RADIUS);
        int bk = (int)fabsf(fmodf(v, (float)TSZ));
        atomicAdd(&shist[h * TSZ + bk], 1);
    }
    __syncthreads();
    for (int e = tid; e < HASH * TSZ; e += 256) {
        int v = shist[e];
        if (v) atomicAdd(&g_hist[e], v);
    }
}

// ---------------- 4: argmax ----------------
__global__ void argmax_kernel() {
    int w = threadIdx.x >> 5, lane = threadIdx.x & 31;
    int best = -1, bidx = 0;
    for (int j = lane; j < TSZ; j += 32) {
        int c = g_hist[w * TSZ + j];
        if (c > best) { best = c; bidx = j; }
    }
    #pragma unroll
    for (int off = 16; off; off >>= 1) {
        int ob = __shfl_down_sync(0xffffffffu, best, off);
        int oi = __shfl_down_sync(0xffffffffu, bidx, off);
        if (ob > best || (ob == best && oi < bidx)) { best = ob; bidx = oi; }
    }
    if (lane == 0) g_voted[w] = bidx;
}

// ---------------- 5: mask ----------------
__global__ void mask_kernel() {
    __shared__ int sv[HASH];
    if (threadIdx.x < HASH) sv[threadIdx.x] = g_voted[threadIdx.x];
    __syncthreads();
    int o = threadIdx.x, m = 0;
    #pragma unroll
    for (int h = 0; h < HASH; h++) {
        int kb = g_kbuckets[h * OCH + o];
        #pragma unroll
        for (int j = 0; j < HASH; j++) m |= (kb == sv[j]);
    }
    g_mask[o] = m;
}

// ---------------- 6: warp-MMA implicit-GEMM conv (fp16, pitch 160) ----------
// CTA 512 thr: M=128 oc (ocg half), N=256 px (2 rows), K=576.
// Warp grid 4(M)x4(N); warp tile 32x64. Single fp16 MMA per k16 chunk.
// Pitch 160B => LDS.64 phases are bank-conflict-free (8*lr + 2*lj pattern).
#define PITCH   160
#define T_OFF   512
#define T_PER   83200         // 4*130*160
#define A_OFF   83712         // 512 + T_PER
#define A_BUF   20480         // 128*160
#define SMEM_CONV 124672      // A_OFF + 2*A_BUF

__device__ __forceinline__ void copyA_tap(uint32_t sb, int t, int buf, int ocg, int tid) {
    const char* gb = (const char*)g_wq;
    #pragma unroll
    for (int q = 0; q < 2; q++) {
        int e = q * 512 + tid;            // 0..1023
        int oc = e >> 3, j = e & 7;
        const char* src = gb + ((size_t)t * 256 + ocg * 128 + oc) * 128 + j * 16;
        uint32_t dst = sb + A_OFF + buf * A_BUF + oc * PITCH + j * 16;
        cp_async16(dst, src);
    }
}

__global__ void __launch_bounds__(512, 1)
conv_mma_kernel(const float* __restrict__ x, float* __restrict__ out) {
    extern __shared__ __align__(16) char smem[];
    uint32_t sb = smem_u32(smem);
    int tid = threadIdx.x, wid = tid >> 5, lane = tid & 31;
    int ocg = blockIdx.x, rp = blockIdx.y, img = blockIdx.z;
    int y0 = rp * 2;

    float* smask = (float*)smem;
    if (tid < 128) smask[tid] = g_mask[ocg * 128 + tid] ? 1.f : 0.f;

    // prefetch A tap 0
    copyA_tap(sb, 0, 0, ocg, tid);
    CP_COMMIT();

    // zero T (padding cols + OOB rows stay zero)
    {
        uint4 z = {0, 0, 0, 0};
        uint4* tz = (uint4*)(smem + T_OFF);
        for (int e = tid; e < T_PER / 16; e += 512) tz[e] = z;
    }
    __syncthreads();

    // build T interior: rows y0-1 .. y0+2, fp16, channel-permuted 128B rows
    for (int e = tid; e < 4 * C_IN * HW; e += 512) {
        int rr = e >> 13, rem = e & 8191;
        int c = rem >> 7, xc = rem & 127;
        int y = y0 - 1 + rr;
        if (y >= 0 && y < HW) {
            float v = x[((img * C_IN + c) * HW + y) * HW + xc];
            int off = (rr * 130 + xc + 1) * PITCH + cslot(c);
            *(__half*)(smem + T_OFF + off) = __float2half(v);
        }
    }
    __syncthreads();

    int m0   = (wid & 3) * 32;
    int n0w  = (wid >> 2) * 64;
    int yrel = n0w >> 7;
    int x0w  = n0w & 127;
    int lr   = lane >> 2;        // 0..7
    int lj   = lane & 3;         // 0..3

    float acc[2][8][4];
    #pragma unroll
    for (int mt = 0; mt < 2; mt++)
        #pragma unroll
        for (int nt = 0; nt < 8; nt++)
            #pragma unroll
            for (int q = 0; q < 4; q++) acc[mt][nt][q] = 0.f;

    for (int t = 0; t < 9; t++) {
        int kh = t / 3, kw = t % 3, buf = t & 1;
        CP_WAIT0();
        __syncthreads();
        if (t < 8) { copyA_tap(sb, t + 1, buf ^ 1, ocg, tid); CP_COMMIT(); }

        const char* Ah = smem + A_OFF + buf * A_BUF;
        int rr = yrel + kh;
        const char* Tb = smem + T_OFF + (rr * 130 + kw) * PITCH;

        #pragma unroll
        for (int ks = 0; ks < 4; ks++) {
            int fo = ks * 32 + lj * 8;
            uint32_t ah[2][4];
            #pragma unroll
            for (int mt = 0; mt < 2; mt++) {
                int r0 = (m0 + mt * 16 + lr) * PITCH + fo;
                int r8 = r0 + 8 * PITCH;
                uint2 w0 = *(const uint2*)(Ah + r0);
                uint2 w8 = *(const uint2*)(Ah + r8);
                ah[mt][0] = w0.x; ah[mt][2] = w0.y;
                ah[mt][1] = w8.x; ah[mt][3] = w8.y;
            }
            #pragma unroll
            for (int nt = 0; nt < 8; nt++) {
                int xo = (x0w + nt * 8 + lr) * PITCH + fo;
                uint2 bv = *(const uint2*)(Tb + xo);
                mma16816(acc[0][nt], ah[0][0], ah[0][1], ah[0][2], ah[0][3], bv.x, bv.y);
                mma16816(acc[1][nt], ah[1][0], ah[1][1], ah[1][2], ah[1][3], bv.x, bv.y);
            }
        }
    }

    // epilogue: masked stores
    int y = y0 + yrel;
    #pragma unroll
    for (int mt = 0; mt < 2; mt++) {
        int mrow = m0 + mt * 16 + lr;
        float mk0 = smask[mrow];
        float mk1 = smask[mrow + 8];
        int oc0 = ocg * 128 + mrow;
        size_t b0 = ((size_t)(img * OCH + oc0) * HW + y) * HW;
        size_t b1 = b0 + (size_t)8 * HW * HW;
        #pragma unroll
        for (int nt = 0; nt < 8; nt++) {
            int xcol = x0w + nt * 8 + lj * 2;
            float2 v0 = { acc[mt][nt][0] * mk0, acc[mt][nt][1] * mk0 };
            float2 v1 = { acc[mt][nt][2] * mk1, acc[mt][nt][3] * mk1 };
            *(float2*)(out + b0 + xcol) = v0;
            *(float2*)(out + b1 + xcol) = v1;
        }
    }
}

// ---------------- launch ----------------
extern "C" void kernel_launch(void* const* d_in, const int* in_sizes, int n_in,
                              void* d_out, int out_size) {
    const float* x = (const float*)d_in[0];   // [32,64,128,128]
    const float* w = (const float*)d_in[1];   // [256,64,3,3]
    const float* a = (const float*)d_in[2];   // [8,67,3,3]
    const float* b = (const float*)d_in[3];   // [8]
    float* out = (float*)d_out;               // [32,256,128,128]

    cudaFuncSetAttribute(conv_mma_kernel,
                         cudaFuncAttributeMaxDynamicSharedMemorySize, SMEM_CONV);

    zero_hist_kernel<<<16, 256>>>();
    norms_kernel<<<1, 256>>>(w);
    kbuckets_kernel<<<256, 256>>>(w, a, b);
    wprep_kernel<<<576, 256>>>(w);
    vote_kernel<<<dim3(8, 8, NB), 256>>>(x, a, b);
    argmax_kernel<<<1, 256>>>();
    mask_kernel<<<1, 256>>>();
    conv_mma_kernel<<<dim3(2, 64, NB), 512, SMEM_CONV>>>(x, out);
}